// round 6
// baseline (speedup 1.0000x reference)
#include <cuda_runtime.h>

// ---------------------------------------------------------------------------
// DecGreenNet_product_CP3 — algebraically collapsed:
//   out[i] = c + sum_h v[h] * tanh(x_i . Wx1[:,h] + bx1[h])
//   s_br = (sum_n y_n h_n) @ Wq2_br + (sum_n y_n) * bq2_br
//   rhs[b,d,f] = sum_x s0[b,x] s1[d,x] s2[f,x];  v = Wx2 @ rhs;  c = bx2 . rhs
// ---------------------------------------------------------------------------

#define PI_F 3.14159265358979323846f

__device__ float g_part[3][64][128];   // per-branch per-chunk weighted-tanh sums
__device__ float g_party[3][64];       // per-branch per-chunk sum of y
__device__ float g_v[512];
__device__ float g_c;

__device__ __forceinline__ float tanh_mufu(float x) {
    float y;
    asm("tanh.approx.f32 %0, %1;" : "=f"(y) : "f"(x));
    return y;
}

// accurate-enough tanh (~1e-6 abs err) from 2 MUFU ops — branch path only,
// where 8192-term sums could amplify tanh.approx's 1.5e-4 error.
__device__ __forceinline__ float tanh_acc(float z) {
    float e = __expf(2.0f * z);                 // mul + ex2
    return 1.0f - __fdividef(2.0f, e + 1.0f);   // rcp path + fma
}

// ---------------------------------------------------------------------------
// Kernel A: branch partials.  grid (64, 3) x 1024 threads.
// thread (j = t&127, grp = t>>7) accumulates 16 nodes; 8 groups reduced in smem.
// ---------------------------------------------------------------------------
__global__ void __launch_bounds__(1024) kernelA(
        const float* __restrict__ q0, const float* __restrict__ q1,
        const float* __restrict__ q2,
        const float* __restrict__ w0, const float* __restrict__ w1,
        const float* __restrict__ w2,
        const float* __restrict__ c0, const float* __restrict__ c1,
        const float* __restrict__ c2,
        const float* __restrict__ eq)
{
    const int br = blockIdx.y;
    const float* qx = (br == 0) ? q0 : ((br == 1) ? q1 : q2);
    const float* W1 = (br == 0) ? w0 : ((br == 1) ? w1 : w2);
    const float* B1 = (br == 0) ? c0 : ((br == 1) ? c1 : c2);

    __shared__ float sq[128];
    __shared__ float sy[128];
    __shared__ float pacc[8][128];

    const int t   = threadIdx.x;
    const int j   = t & 127;
    const int grp = t >> 7;           // 0..7

    if (t < 128) {
        const float pe = PI_F * eq[0];
        const float q  = qx[blockIdx.x * 128 + t];
        sq[t] = q;
        sy[t] = sinf(pe * q);
    }
    __syncthreads();

    const float w  = W1[j];
    const float b  = B1[j];
    const int   n0 = grp * 16;
    float acc = 0.f;
#pragma unroll
    for (int n = n0; n < n0 + 16; n++) {
        acc = fmaf(sy[n], tanh_acc(fmaf(sq[n], w, b)), acc);
    }
    pacc[grp][j] = acc;

    // warp 4 (t 128..159) reduces sum_y while others sync
    if (t >= 128 && t < 160) {
        const int lane = t - 128;
        float s = sy[lane * 4] + sy[lane * 4 + 1] + sy[lane * 4 + 2] + sy[lane * 4 + 3];
#pragma unroll
        for (int o = 16; o; o >>= 1) s += __shfl_xor_sync(0xffffffffu, s, o);
        if (lane == 0) g_party[br][blockIdx.x] = s;
    }
    __syncthreads();

    if (t < 128) {
        float s = 0.f;
#pragma unroll
        for (int g = 0; g < 8; g++) s += pacc[g][t];
        g_part[br][blockIdx.x][t] = s;
    }
}

// ---------------------------------------------------------------------------
// Kernel BV: grid 64 x 512.  Every block REDUNDANTLY computes the tiny
// phases 1-3 (identical, deterministic results), then computes its own
// 8 rows of v = Wx2 @ rhs.  Eliminates the serial single-block kernelB
// and one launch; the 1MB Wx2 stream stays spread over 64 SMs.
// ---------------------------------------------------------------------------
__global__ void __launch_bounds__(512) kernelBV(
        const float* __restrict__ Wq02, const float* __restrict__ bq02,
        const float* __restrict__ Wq12, const float* __restrict__ bq12,
        const float* __restrict__ Wq22, const float* __restrict__ bq22,
        const float* __restrict__ bx2,  const float* __restrict__ Wx2)
{
    __shared__ float wh[3][128];
    __shared__ float sumy[3];
    __shared__ float s_sh[3][128];
    __shared__ __align__(16) float rsh[512];
    __shared__ float red[512];

    const int t = threadIdx.x;

    // phase 1: reduce per-chunk partials
    if (t < 384) {
        const int br = t >> 7, j = t & 127;
        float a = 0.f;
#pragma unroll 8
        for (int blk = 0; blk < 64; blk++) a += g_part[br][blk][j];
        wh[br][j] = a;
    } else if (t < 387) {
        const int br = t - 384;
        float s = 0.f;
#pragma unroll 8
        for (int blk = 0; blk < 64; blk++) s += g_party[br][blk];
        sumy[br] = s;
    }
    __syncthreads();

    // phase 2: s_br = wh_br @ Wq2_br + sumy_br * bq2_br (coalesced rows)
    if (t < 384) {
        const int br = t >> 7, c = t & 127;
        const float* W2 = (br == 0) ? Wq02 : ((br == 1) ? Wq12 : Wq22);
        const float* B2 = (br == 0) ? bq02 : ((br == 1) ? bq12 : bq22);
        float a = sumy[br] * B2[c];
#pragma unroll 8
        for (int j = 0; j < 128; j++) a = fmaf(wh[br][j], W2[j * 128 + c], a);
        s_sh[br][c] = a;                   // c = b*16 + x
    }
    __syncthreads();

    // phase 3: rhs + c
    if (t < 512) {
        const int b = t >> 6, d = (t >> 3) & 7, f = t & 7;
        float r = 0.f;
#pragma unroll
        for (int x = 0; x < 16; x++)
            r += s_sh[0][b * 16 + x] * s_sh[1][d * 16 + x] * s_sh[2][f * 16 + x];
        rsh[t] = r;
        red[t] = bx2[t] * r;
    }
    __syncthreads();
    for (int off = 256; off > 0; off >>= 1) {
        if (t < off) red[t] += red[t + off];
        __syncthreads();
    }
    if (blockIdx.x == 0 && t == 0) g_c = red[0];

    // phase V: 8 rows of v per block (warp per row; warps 8..15 idle)
    const int wp   = t >> 5;
    const int lane = t & 31;
    if (wp < 8) {
        const int h = blockIdx.x * 8 + wp;
        const float4* row4 = (const float4*)(Wx2 + h * 512);
        const float4* r4   = (const float4*)rsh;
        float a = 0.f;
#pragma unroll
        for (int k = lane; k < 128; k += 32) {
            const float4 w = row4[k];
            const float4 r = r4[k];
            a = fmaf(w.x, r.x, fmaf(w.y, r.y, fmaf(w.z, r.z, fmaf(w.w, r.w, a))));
        }
#pragma unroll
        for (int o = 16; o; o >>= 1) a += __shfl_xor_sync(0xffffffffu, a, o);
        if (lane == 0) g_v[h] = a;
    }
}

// ---------------------------------------------------------------------------
// Kernel C: main batch.  256 threads = 8 rowgroups(x8 rows) x 32 h-splits(x16 h).
// R=8: one LDS.128+LDS feeds 8 independent tanh chains (2x the ILP of R5's
// R=4, which left MUFU only ~55% busy / latency-bound).
// Per thread: 16 iters.  grid = Bn/64 = 1024 blocks.
// ---------------------------------------------------------------------------
__global__ void __launch_bounds__(256) kernelC(const float* __restrict__ X,
                                               const float* __restrict__ Wx1,
                                               const float* __restrict__ bx1,
                                               float* __restrict__ out, int Bn)
{
    __shared__ float4 wt[512];            // {Wx1[0,h], Wx1[1,h], Wx1[2,h], bx1[h]}
    __shared__ float  vs[512];
    __shared__ __align__(16) float pp[32 * 64];  // [h-split][row 0..63]

    const int t = threadIdx.x;
#pragma unroll
    for (int h = t; h < 512; h += 256) {
        wt[h] = make_float4(Wx1[h], Wx1[512 + h], Wx1[1024 + h], bx1[h]);
        vs[h] = g_v[h];
    }
    __syncthreads();

    const int rg = t & 7;         // rowgroup (8 rows each)
    const int hs = t >> 3;        // 0..31 h-splits
    const int h0 = hs << 4;       // 16 h per split
    const int i0 = blockIdx.x * 64 + rg * 8;

    float xv[24];                 // 8 rows x 3 coords
    if (i0 + 7 < Bn) {
        // i0 multiple of 8 -> byte offset i0*12 is 32B-aligned
        const float4* xp = (const float4*)(X + i0 * 3);
#pragma unroll
        for (int q = 0; q < 6; q++) {
            const float4 v4 = xp[q];
            xv[q * 4 + 0] = v4.x; xv[q * 4 + 1] = v4.y;
            xv[q * 4 + 2] = v4.z; xv[q * 4 + 3] = v4.w;
        }
    } else {
#pragma unroll
        for (int q = 0; q < 24; q++) {
            const int gi = i0 * 3 + q;
            xv[q] = (gi < Bn * 3) ? X[gi] : 0.f;
        }
    }

    float a[8];
#pragma unroll
    for (int r = 0; r < 8; r++) a[r] = 0.f;

#pragma unroll
    for (int hh = 0; hh < 16; hh++) {
        const float4 w  = wt[h0 + hh];
        const float  vv = vs[h0 + hh];
#pragma unroll
        for (int r = 0; r < 8; r++) {
            const float z = fmaf(xv[3 * r + 2], w.z,
                           fmaf(xv[3 * r + 1], w.y,
                           fmaf(xv[3 * r + 0], w.x, w.w)));
            a[r] = fmaf(vv, tanh_mufu(z), a[r]);
        }
    }

    // store 8 partials: pp[hs*64 + rg*8 + r]  (two STS.128, 32B-aligned)
    float* prow = pp + hs * 64 + rg * 8;
    ((float4*)prow)[0] = make_float4(a[0], a[1], a[2], a[3]);
    ((float4*)prow)[1] = make_float4(a[4], a[5], a[6], a[7]);
    __syncthreads();

    if (t < 64) {
        float s = g_c;
#pragma unroll 8
        for (int h2 = 0; h2 < 32; h2++) s += pp[h2 * 64 + t];
        const int oi = blockIdx.x * 64 + t;
        if (oi < Bn) out[oi] = s;
    }
}

// ---------------------------------------------------------------------------
extern "C" void kernel_launch(void* const* d_in, const int* in_sizes, int n_in,
                              void* d_out, int out_size)
{
    const float* input = (const float*)d_in[0];
    const float* eq    = (const float*)d_in[1];
    const float* q0    = (const float*)d_in[2];
    const float* q1    = (const float*)d_in[3];
    const float* q2    = (const float*)d_in[4];
    const float* Wx1   = (const float*)d_in[5];
    const float* bx1   = (const float*)d_in[6];
    const float* Wx2   = (const float*)d_in[7];
    const float* bx2   = (const float*)d_in[8];
    const float* Wq01  = (const float*)d_in[9];
    const float* bq01  = (const float*)d_in[10];
    const float* Wq02  = (const float*)d_in[11];
    const float* bq02  = (const float*)d_in[12];
    const float* Wq11  = (const float*)d_in[13];
    const float* bq11  = (const float*)d_in[14];
    const float* Wq12  = (const float*)d_in[15];
    const float* bq12  = (const float*)d_in[16];
    const float* Wq21  = (const float*)d_in[17];
    const float* bq21  = (const float*)d_in[18];
    const float* Wq22  = (const float*)d_in[19];
    const float* bq22  = (const float*)d_in[20];

    const int N  = in_sizes[2];          // 8192 quad nodes
    const int Bn = in_sizes[0] / 3;      // 65536 rows
    const int nblkA = N / 128;           // 64

    kernelA<<<dim3(nblkA, 3), 1024>>>(q0, q1, q2,
                                      Wq01, Wq11, Wq21,
                                      bq01, bq11, bq21, eq);
    kernelBV<<<64, 512>>>(Wq02, bq02, Wq12, bq12, Wq22, bq22, bx2, Wx2);
    kernelC<<<(Bn + 63) / 64, 256>>>(input, Wx1, bx1, (float*)d_out, Bn);
}

// round 7
// speedup vs baseline: 1.0200x; 1.0200x over previous
#include <cuda_runtime.h>

// ---------------------------------------------------------------------------
// DecGreenNet_product_CP3 — algebraically collapsed:
//   out[i] = c + sum_h v[h] * tanh(x_i . Wx1[:,h] + bx1[h])
//   s_br = (sum_n y_n h_n) @ Wq2_br + (sum_n y_n) * bq2_br
//   rhs[b,d,f] = sum_x s0[b,x] s1[d,x] s2[f,x];  v = Wx2 @ rhs;  c = bx2 . rhs
// ---------------------------------------------------------------------------

#define PI_F 3.14159265358979323846f

__device__ float g_part[3][64][128];   // per-branch per-chunk weighted-tanh sums
__device__ float g_party[3][64];       // per-branch per-chunk sum of y
__device__ float g_v[512];
__device__ float g_c;

__device__ __forceinline__ float tanh_mufu(float x) {
    float y;
    asm("tanh.approx.f32 %0, %1;" : "=f"(y) : "f"(x));
    return y;
}

// accurate-enough tanh (~1e-6 abs err) from 2 MUFU ops — branch path only,
// where 8192-term sums could amplify tanh.approx's 1.5e-4 error.
__device__ __forceinline__ float tanh_acc(float z) {
    float e = __expf(2.0f * z);                 // mul + ex2
    return 1.0f - __fdividef(2.0f, e + 1.0f);   // rcp path + fma
}

// ---------------------------------------------------------------------------
// Kernel A: branch partials.  grid (64, 3) x 1024 threads.
// thread (j = t&127, grp = t>>7) accumulates 16 nodes; 8 groups reduced in smem.
// ---------------------------------------------------------------------------
__global__ void __launch_bounds__(1024) kernelA(
        const float* __restrict__ q0, const float* __restrict__ q1,
        const float* __restrict__ q2,
        const float* __restrict__ w0, const float* __restrict__ w1,
        const float* __restrict__ w2,
        const float* __restrict__ c0, const float* __restrict__ c1,
        const float* __restrict__ c2,
        const float* __restrict__ eq)
{
    const int br = blockIdx.y;
    const float* qx = (br == 0) ? q0 : ((br == 1) ? q1 : q2);
    const float* W1 = (br == 0) ? w0 : ((br == 1) ? w1 : w2);
    const float* B1 = (br == 0) ? c0 : ((br == 1) ? c1 : c2);

    __shared__ float sq[128];
    __shared__ float sy[128];
    __shared__ float pacc[8][128];

    const int t   = threadIdx.x;
    const int j   = t & 127;
    const int grp = t >> 7;           // 0..7

    if (t < 128) {
        const float pe = PI_F * eq[0];
        const float q  = qx[blockIdx.x * 128 + t];
        sq[t] = q;
        sy[t] = sinf(pe * q);
    }
    __syncthreads();

    const float w  = W1[j];
    const float b  = B1[j];
    const int   n0 = grp * 16;
    float acc = 0.f;
#pragma unroll
    for (int n = n0; n < n0 + 16; n++) {
        acc = fmaf(sy[n], tanh_acc(fmaf(sq[n], w, b)), acc);
    }
    pacc[grp][j] = acc;

    // warp 4 (t 128..159) reduces sum_y while others sync
    if (t >= 128 && t < 160) {
        const int lane = t - 128;
        float s = sy[lane * 4] + sy[lane * 4 + 1] + sy[lane * 4 + 2] + sy[lane * 4 + 3];
#pragma unroll
        for (int o = 16; o; o >>= 1) s += __shfl_xor_sync(0xffffffffu, s, o);
        if (lane == 0) g_party[br][blockIdx.x] = s;
    }
    __syncthreads();

    if (t < 128) {
        float s = 0.f;
#pragma unroll
        for (int g = 0; g < 8; g++) s += pacc[g][t];
        g_part[br][blockIdx.x][t] = s;
    }
}

// ---------------------------------------------------------------------------
// Kernel BV: grid 64 x 512.  Every block redundantly computes the tiny
// phases 1-3 (identical deterministic results), then its own 8 rows of
// v = Wx2 @ rhs.  Keeps the 1MB Wx2 stream spread over 64 SMs.
// ---------------------------------------------------------------------------
__global__ void __launch_bounds__(512) kernelBV(
        const float* __restrict__ Wq02, const float* __restrict__ bq02,
        const float* __restrict__ Wq12, const float* __restrict__ bq12,
        const float* __restrict__ Wq22, const float* __restrict__ bq22,
        const float* __restrict__ bx2,  const float* __restrict__ Wx2)
{
    __shared__ float wh[3][128];
    __shared__ float sumy[3];
    __shared__ float s_sh[3][128];
    __shared__ __align__(16) float rsh[512];
    __shared__ float red[512];

    const int t = threadIdx.x;

    // phase 1: reduce per-chunk partials (deep unroll -> high MLP)
    if (t < 384) {
        const int br = t >> 7, j = t & 127;
        float a = 0.f;
#pragma unroll 16
        for (int blk = 0; blk < 64; blk++) a += g_part[br][blk][j];
        wh[br][j] = a;
    } else if (t < 387) {
        const int br = t - 384;
        float s = 0.f;
#pragma unroll 16
        for (int blk = 0; blk < 64; blk++) s += g_party[br][blk];
        sumy[br] = s;
    }
    __syncthreads();

    // phase 2: s_br = wh_br @ Wq2_br + sumy_br * bq2_br (coalesced columns)
    if (t < 384) {
        const int br = t >> 7, c = t & 127;
        const float* W2 = (br == 0) ? Wq02 : ((br == 1) ? Wq12 : Wq22);
        const float* B2 = (br == 0) ? bq02 : ((br == 1) ? bq12 : bq22);
        float a = sumy[br] * B2[c];
#pragma unroll 16
        for (int j = 0; j < 128; j++) a = fmaf(wh[br][j], W2[j * 128 + c], a);
        s_sh[br][c] = a;                   // c = b*16 + x
    }
    __syncthreads();

    // phase 3: rhs + c
    if (t < 512) {
        const int b = t >> 6, d = (t >> 3) & 7, f = t & 7;
        float r = 0.f;
#pragma unroll
        for (int x = 0; x < 16; x++)
            r += s_sh[0][b * 16 + x] * s_sh[1][d * 16 + x] * s_sh[2][f * 16 + x];
        rsh[t] = r;
        red[t] = bx2[t] * r;
    }
    __syncthreads();
    for (int off = 256; off > 0; off >>= 1) {
        if (t < off) red[t] += red[t + off];
        __syncthreads();
    }
    if (blockIdx.x == 0 && t == 0) g_c = red[0];

    // phase V: 8 rows of v per block (warp per row; warps 8..15 idle)
    const int wp   = t >> 5;
    const int lane = t & 31;
    if (wp < 8) {
        const int h = blockIdx.x * 8 + wp;
        const float4* row4 = (const float4*)(Wx2 + h * 512);
        const float4* r4   = (const float4*)rsh;
        float a = 0.f;
#pragma unroll
        for (int k = lane; k < 128; k += 32) {
            const float4 w = row4[k];
            const float4 r = r4[k];
            a = fmaf(w.x, r.x, fmaf(w.y, r.y, fmaf(w.z, r.z, fmaf(w.w, r.w, a))));
        }
#pragma unroll
        for (int o = 16; o; o >>= 1) a += __shfl_xor_sync(0xffffffffu, a, o);
        if (lane == 0) g_v[h] = a;
    }
}

// ---------------------------------------------------------------------------
// Kernel C: main batch.  512 threads = 16 warps; warp = one h-split of 32 h,
// lane = 8 consecutive rows.  EVERY weight LDS is a pure warp broadcast
// (conflict-free) — R6's rg/hs interleave caused 4-way bank conflicts.
// Per thread: 32 iters x (dot3 + tanh.approx + acc) over 8 independent rows.
// Block covers 256 rows; grid = 256 blocks; MUFU is the binding pipe.
// ---------------------------------------------------------------------------
__global__ void __launch_bounds__(512) kernelC(const float* __restrict__ X,
                                               const float* __restrict__ Wx1,
                                               const float* __restrict__ bx1,
                                               float* __restrict__ out, int Bn)
{
    __shared__ float4 wt[512];        // {Wx1[0,h], Wx1[1,h], Wx1[2,h], bx1[h]}
    __shared__ float  vs[512];
    __shared__ __align__(16) float pp[16][256];  // [warp][row-in-block]

    const int t = threadIdx.x;
    wt[t] = make_float4(Wx1[t], Wx1[512 + t], Wx1[1024 + t], bx1[t]);
    vs[t] = g_v[t];
    __syncthreads();

    const int wp   = t >> 5;          // 0..15  (h-split)
    const int lane = t & 31;          // 8 rows per lane
    const int h0   = wp << 5;         // 32 h per warp
    const int r0   = blockIdx.x * 256 + lane * 8;

    float xv[24];                     // 8 rows x 3 coords
    if (r0 + 7 < Bn) {
        // r0 multiple of 8 -> byte offset r0*12 is 32B-aligned; 96B contiguous
        const float4* xp = (const float4*)(X + r0 * 3);
#pragma unroll
        for (int q = 0; q < 6; q++) {
            const float4 v4 = xp[q];
            xv[q * 4 + 0] = v4.x; xv[q * 4 + 1] = v4.y;
            xv[q * 4 + 2] = v4.z; xv[q * 4 + 3] = v4.w;
        }
    } else {
#pragma unroll
        for (int q = 0; q < 24; q++) {
            const int gi = r0 * 3 + q;
            xv[q] = (gi < Bn * 3) ? X[gi] : 0.f;
        }
    }

    float a[8];
#pragma unroll
    for (int r = 0; r < 8; r++) a[r] = 0.f;

#pragma unroll 8
    for (int hh = 0; hh < 32; hh++) {
        const float4 w  = wt[h0 + hh];    // warp-uniform address: broadcast
        const float  vv = vs[h0 + hh];    // broadcast
#pragma unroll
        for (int r = 0; r < 8; r++) {
            const float z = fmaf(xv[3 * r + 2], w.z,
                           fmaf(xv[3 * r + 1], w.y,
                           fmaf(xv[3 * r + 0], w.x, w.w)));
            a[r] = fmaf(vv, tanh_mufu(z), a[r]);
        }
    }

    // pp[wp][lane*8 + r]: contiguous 32B per lane -> conflict-free STS.128
    float* prow = &pp[wp][lane * 8];
    ((float4*)prow)[0] = make_float4(a[0], a[1], a[2], a[3]);
    ((float4*)prow)[1] = make_float4(a[4], a[5], a[6], a[7]);
    __syncthreads();

    if (t < 256) {
        float s = g_c;
#pragma unroll
        for (int w2 = 0; w2 < 16; w2++) s += pp[w2][t];
        const int oi = blockIdx.x * 256 + t;
        if (oi < Bn) out[oi] = s;
    }
}

// ---------------------------------------------------------------------------
extern "C" void kernel_launch(void* const* d_in, const int* in_sizes, int n_in,
                              void* d_out, int out_size)
{
    const float* input = (const float*)d_in[0];
    const float* eq    = (const float*)d_in[1];
    const float* q0    = (const float*)d_in[2];
    const float* q1    = (const float*)d_in[3];
    const float* q2    = (const float*)d_in[4];
    const float* Wx1   = (const float*)d_in[5];
    const float* bx1   = (const float*)d_in[6];
    const float* Wx2   = (const float*)d_in[7];
    const float* bx2   = (const float*)d_in[8];
    const float* Wq01  = (const float*)d_in[9];
    const float* bq01  = (const float*)d_in[10];
    const float* Wq02  = (const float*)d_in[11];
    const float* bq02  = (const float*)d_in[12];
    const float* Wq11  = (const float*)d_in[13];
    const float* bq11  = (const float*)d_in[14];
    const float* Wq12  = (const float*)d_in[15];
    const float* bq12  = (const float*)d_in[16];
    const float* Wq21  = (const float*)d_in[17];
    const float* bq21  = (const float*)d_in[18];
    const float* Wq22  = (const float*)d_in[19];
    const float* bq22  = (const float*)d_in[20];

    const int N  = in_sizes[2];          // 8192 quad nodes
    const int Bn = in_sizes[0] / 3;      // 65536 rows
    const int nblkA = N / 128;           // 64

    kernelA<<<dim3(nblkA, 3), 1024>>>(q0, q1, q2,
                                      Wq01, Wq11, Wq21,
                                      bq01, bq11, bq21, eq);
    kernelBV<<<64, 512>>>(Wq02, bq02, Wq12, bq12, Wq22, bq22, bx2, Wx2);
    kernelC<<<(Bn + 255) / 256, 512>>>(input, Wx1, bx1, (float*)d_out, Bn);
}

// round 8
// speedup vs baseline: 1.0212x; 1.0011x over previous
#include <cuda_runtime.h>

// ---------------------------------------------------------------------------
// DecGreenNet_product_CP3 — algebraically collapsed:
//   out[i] = c + sum_h v[h] * tanh(x_i . Wx1[:,h] + bx1[h])
//   s_br = (sum_n y_n h_n) @ Wq2_br + (sum_n y_n) * bq2_br
//   rhs[b,d,f] = sum_x s0[b,x] s1[d,x] s2[f,x];  v = Wx2 @ rhs;  c = bx2 . rhs
// ---------------------------------------------------------------------------

#define PI_F 3.14159265358979323846f

__device__ float g_part[3][128][128];  // per-branch per-chunk weighted-tanh sums
__device__ float g_party[3][128];      // per-branch per-chunk sum of y
__device__ float g_v[512];
__device__ float g_c;

__device__ __forceinline__ float tanh_mufu(float x) {
    float y;
    asm("tanh.approx.f32 %0, %1;" : "=f"(y) : "f"(x));
    return y;
}

// accurate-enough tanh (~1e-6 abs err) from 2 MUFU ops — branch path only,
// where 8192-term sums could amplify tanh.approx's 1.5e-4 error.
__device__ __forceinline__ float tanh_acc(float z) {
    float e = __expf(2.0f * z);                 // mul + ex2
    return 1.0f - __fdividef(2.0f, e + 1.0f);   // rcp path + fma
}

// ---------------------------------------------------------------------------
// Kernel A: branch partials.  grid (128, 3) x 512 threads; chunk = 64 nodes.
// NO barrier before the main loop: each warp loads its own 16 nodes into
// lanes 0..15 and broadcasts via shfl.  (R7 version serialized every block
// behind a 128-thread LDG+sinf head + __syncthreads -> 7.8us at issue=36%.)
// warp w (0..15): grp = w>>2 selects 16 nodes, j = (w&3)*32+lane.
// 384 blocks x 16 warps = 6144 warps, all resident in one wave.
// ---------------------------------------------------------------------------
__global__ void __launch_bounds__(512) kernelA(
        const float* __restrict__ q0, const float* __restrict__ q1,
        const float* __restrict__ q2,
        const float* __restrict__ w0, const float* __restrict__ w1,
        const float* __restrict__ w2,
        const float* __restrict__ c0, const float* __restrict__ c1,
        const float* __restrict__ c2,
        const float* __restrict__ eq)
{
    const int br = blockIdx.y;
    const float* qx = (br == 0) ? q0 : ((br == 1) ? q1 : q2);
    const float* W1 = (br == 0) ? w0 : ((br == 1) ? w1 : w2);
    const float* B1 = (br == 0) ? c0 : ((br == 1) ? c1 : c2);

    __shared__ float pacc[4][128];
    __shared__ float sy64[64];

    const int t    = threadIdx.x;
    const int lane = t & 31;
    const int w    = t >> 5;          // 0..15
    const int grp  = w >> 2;          // 0..3 -> which 16 nodes
    const int j    = ((w & 3) << 5) + lane;

    const float pe = PI_F * eq[0];

    float q = 0.f, y = 0.f;
    if (lane < 16) {
        q = qx[blockIdx.x * 64 + grp * 16 + lane];
        y = sinf(pe * q);
        if ((w & 3) == 0) sy64[grp * 16 + lane] = y;   // for sum_y only
    }

    const float wj = W1[j];
    const float bj = B1[j];
    float acc = 0.f;
#pragma unroll
    for (int k = 0; k < 16; k++) {
        const float qk = __shfl_sync(0xffffffffu, q, k);
        const float yk = __shfl_sync(0xffffffffu, y, k);
        acc = fmaf(yk, tanh_acc(fmaf(qk, wj, bj)), acc);
    }
    pacc[grp][j] = acc;
    __syncthreads();

    if (t < 128) {
        g_part[br][blockIdx.x][t] =
            pacc[0][t] + pacc[1][t] + pacc[2][t] + pacc[3][t];
    } else if (w == 4) {              // one warp reduces sum_y
        float s = sy64[lane] + sy64[lane + 32];
#pragma unroll
        for (int o = 16; o; o >>= 1) s += __shfl_xor_sync(0xffffffffu, s, o);
        if (lane == 0) g_party[br][blockIdx.x] = s;
    }
}

// ---------------------------------------------------------------------------
// Kernel BV: grid 64 x 512.  Every block redundantly computes the tiny
// phases 1-3 (identical deterministic results), then its own 8 rows of
// v = Wx2 @ rhs.  Keeps the 1MB Wx2 stream spread over 64 SMs.
// ---------------------------------------------------------------------------
__global__ void __launch_bounds__(512) kernelBV(
        const float* __restrict__ Wq02, const float* __restrict__ bq02,
        const float* __restrict__ Wq12, const float* __restrict__ bq12,
        const float* __restrict__ Wq22, const float* __restrict__ bq22,
        const float* __restrict__ bx2,  const float* __restrict__ Wx2)
{
    __shared__ float wh[3][128];
    __shared__ float sumy[3];
    __shared__ float s_sh[3][128];
    __shared__ __align__(16) float rsh[512];
    __shared__ float red[512];

    const int t = threadIdx.x;

    // phase 1: reduce per-chunk partials (128 chunks now)
    if (t < 384) {
        const int br = t >> 7, j = t & 127;
        float a = 0.f;
#pragma unroll 16
        for (int blk = 0; blk < 128; blk++) a += g_part[br][blk][j];
        wh[br][j] = a;
    } else if (t < 387) {
        const int br = t - 384;
        float s = 0.f;
#pragma unroll 16
        for (int blk = 0; blk < 128; blk++) s += g_party[br][blk];
        sumy[br] = s;
    }
    __syncthreads();

    // phase 2: s_br = wh_br @ Wq2_br + sumy_br * bq2_br (coalesced columns)
    if (t < 384) {
        const int br = t >> 7, c = t & 127;
        const float* W2 = (br == 0) ? Wq02 : ((br == 1) ? Wq12 : Wq22);
        const float* B2 = (br == 0) ? bq02 : ((br == 1) ? bq12 : bq22);
        float a = sumy[br] * B2[c];
#pragma unroll 16
        for (int j = 0; j < 128; j++) a = fmaf(wh[br][j], W2[j * 128 + c], a);
        s_sh[br][c] = a;                   // c = b*16 + x
    }
    __syncthreads();

    // phase 3: rhs + c
    if (t < 512) {
        const int b = t >> 6, d = (t >> 3) & 7, f = t & 7;
        float r = 0.f;
#pragma unroll
        for (int x = 0; x < 16; x++)
            r += s_sh[0][b * 16 + x] * s_sh[1][d * 16 + x] * s_sh[2][f * 16 + x];
        rsh[t] = r;
        red[t] = bx2[t] * r;
    }
    __syncthreads();
    for (int off = 256; off > 0; off >>= 1) {
        if (t < off) red[t] += red[t + off];
        __syncthreads();
    }
    if (blockIdx.x == 0 && t == 0) g_c = red[0];

    // phase V: 8 rows of v per block (warp per row; warps 8..15 idle)
    const int wp   = t >> 5;
    const int lane = t & 31;
    if (wp < 8) {
        const int h = blockIdx.x * 8 + wp;
        const float4* row4 = (const float4*)(Wx2 + h * 512);
        const float4* r4   = (const float4*)rsh;
        float a = 0.f;
#pragma unroll
        for (int k = lane; k < 128; k += 32) {
            const float4 w = row4[k];
            const float4 r = r4[k];
            a = fmaf(w.x, r.x, fmaf(w.y, r.y, fmaf(w.z, r.z, fmaf(w.w, r.w, a))));
        }
#pragma unroll
        for (int o = 16; o; o >>= 1) a += __shfl_xor_sync(0xffffffffu, a, o);
        if (lane == 0) g_v[h] = a;
    }
}

// ---------------------------------------------------------------------------
// Kernel C: main batch.  256 threads = 8 warps; warp = 64 h (broadcast LDS,
// conflict-free), lane = 4 rows (R=4 ILP, LSU at ~0.6 of budget).
// Low footprint (~36 regs, 14KB smem) -> ~6 blocks/SM resident; grid 512,
// 4096 warps ALL resident -> maximum MUFU feed.
// ---------------------------------------------------------------------------
__global__ void __launch_bounds__(256) kernelC(const float* __restrict__ X,
                                               const float* __restrict__ Wx1,
                                               const float* __restrict__ bx1,
                                               float* __restrict__ out, int Bn)
{
    __shared__ float4 wt[512];        // {Wx1[0,h], Wx1[1,h], Wx1[2,h], bx1[h]}
    __shared__ float  vs[512];
    __shared__ __align__(16) float pp[8][128];   // [warp][row-in-block]

    const int t = threadIdx.x;
#pragma unroll
    for (int h = t; h < 512; h += 256) {
        wt[h] = make_float4(Wx1[h], Wx1[512 + h], Wx1[1024 + h], bx1[h]);
        vs[h] = g_v[h];
    }
    __syncthreads();

    const int w    = t >> 5;          // 0..7  (h-split)
    const int lane = t & 31;          // 4 rows per lane
    const int h0   = w << 6;          // 64 h per warp
    const int r0   = blockIdx.x * 128 + lane * 4;

    float xv[12];                     // 4 rows x 3 coords
    if (r0 + 3 < Bn) {
        // r0 multiple of 4 -> byte offset r0*12 is 16B-aligned; 48B contiguous
        const float4* xp = (const float4*)(X + r0 * 3);
#pragma unroll
        for (int q = 0; q < 3; q++) {
            const float4 v4 = xp[q];
            xv[q * 4 + 0] = v4.x; xv[q * 4 + 1] = v4.y;
            xv[q * 4 + 2] = v4.z; xv[q * 4 + 3] = v4.w;
        }
    } else {
#pragma unroll
        for (int q = 0; q < 12; q++) {
            const int gi = r0 * 3 + q;
            xv[q] = (gi < Bn * 3) ? X[gi] : 0.f;
        }
    }

    float a0 = 0.f, a1 = 0.f, a2 = 0.f, a3 = 0.f;
#pragma unroll 8
    for (int hh = 0; hh < 64; hh++) {
        const float4 wv = wt[h0 + hh];    // warp-uniform: broadcast
        const float  vv = vs[h0 + hh];    // broadcast
        const float z0 = fmaf(xv[2],  wv.z, fmaf(xv[1],  wv.y, fmaf(xv[0], wv.x, wv.w)));
        const float z1 = fmaf(xv[5],  wv.z, fmaf(xv[4],  wv.y, fmaf(xv[3], wv.x, wv.w)));
        const float z2 = fmaf(xv[8],  wv.z, fmaf(xv[7],  wv.y, fmaf(xv[6], wv.x, wv.w)));
        const float z3 = fmaf(xv[11], wv.z, fmaf(xv[10], wv.y, fmaf(xv[9], wv.x, wv.w)));
        a0 = fmaf(vv, tanh_mufu(z0), a0);
        a1 = fmaf(vv, tanh_mufu(z1), a1);
        a2 = fmaf(vv, tanh_mufu(z2), a2);
        a3 = fmaf(vv, tanh_mufu(z3), a3);
    }

    // pp[w][lane*4 .. +3]: one conflict-free STS.128 per thread
    *((float4*)&pp[w][lane * 4]) = make_float4(a0, a1, a2, a3);
    __syncthreads();

    if (t < 128) {
        float s = g_c;
#pragma unroll
        for (int w2 = 0; w2 < 8; w2++) s += pp[w2][t];
        const int oi = blockIdx.x * 128 + t;
        if (oi < Bn) out[oi] = s;
    }
}

// ---------------------------------------------------------------------------
extern "C" void kernel_launch(void* const* d_in, const int* in_sizes, int n_in,
                              void* d_out, int out_size)
{
    const float* input = (const float*)d_in[0];
    const float* eq    = (const float*)d_in[1];
    const float* q0    = (const float*)d_in[2];
    const float* q1    = (const float*)d_in[3];
    const float* q2    = (const float*)d_in[4];
    const float* Wx1   = (const float*)d_in[5];
    const float* bx1   = (const float*)d_in[6];
    const float* Wx2   = (const float*)d_in[7];
    const float* bx2   = (const float*)d_in[8];
    const float* Wq01  = (const float*)d_in[9];
    const float* bq01  = (const float*)d_in[10];
    const float* Wq02  = (const float*)d_in[11];
    const float* bq02  = (const float*)d_in[12];
    const float* Wq11  = (const float*)d_in[13];
    const float* bq11  = (const float*)d_in[14];
    const float* Wq12  = (const float*)d_in[15];
    const float* bq12  = (const float*)d_in[16];
    const float* Wq21  = (const float*)d_in[17];
    const float* bq21  = (const float*)d_in[18];
    const float* Wq22  = (const float*)d_in[19];
    const float* bq22  = (const float*)d_in[20];

    const int N  = in_sizes[2];          // 8192 quad nodes
    const int Bn = in_sizes[0] / 3;      // 65536 rows
    const int nblkA = N / 64;            // 128 chunks of 64 nodes

    kernelA<<<dim3(nblkA, 3), 512>>>(q0, q1, q2,
                                     Wq01, Wq11, Wq21,
                                     bq01, bq11, bq21, eq);
    kernelBV<<<64, 512>>>(Wq02, bq02, Wq12, bq12, Wq22, bq22, bx2, Wx2);
    kernelC<<<(Bn + 127) / 128, 256>>>(input, Wx1, bx1, (float*)d_out, Bn);
}